// round 10
// baseline (speedup 1.0000x reference)
#include <cuda_runtime.h>
#include <cstdint>

#define N_ROWS   65536
#define DIM      256
#define NCODES   512
#define ND       16777216       // N_ROWS*DIM

typedef unsigned long long ull;

// ---------------- device scratch (no allocations allowed) ----------------
__device__ int   g_idx[N_ROWS];
__device__ float g_cn2[NCODES];            // 0.5*|c|^2
__device__ float g_cout[NCODES * DIM];     // codebook @ W_out^T
__device__ float g_partial[1024];          // per-CTA loss partials
__device__ int   g_mask_mode;              // 0=byte bool, 1=int32, 2=float32

// smem layout (floats) for k_main:
//  zs  [256][68]  @ 0       dim-major z: zs[e*68 + r]          17408
//  Hs  [32][68]   @ 17408   phase A rows, kk-major              2176
//  Ws  [32][258]  @ 19584   phase A W cols, kk-major            8256
//  (Cs [32][130]  @ 17408   phase B codes — aliases dead Hs+Ws, 4160)
//  rowz2[64]      @ 27840
//  lred [8]       @ 27904
#define SM_ZS     0
#define SM_HS     17408
#define SM_WS     19584
#define SM_ROWZ2  27840
#define SM_LRED   27904
#define SM_FLOATS 27912
#define SM_BYTES  (SM_FLOATS * 4)

// ---- packed fp32x2 helpers (FFMA2 reachable only via PTX fma.rn.f32x2) ----
__device__ __forceinline__ ull pk2(float f) {
    ull d; asm("mov.b64 %0, {%1, %1};" : "=l"(d) : "f"(f)); return d;
}
__device__ __forceinline__ void fma2(ull& d, ull a, ull b) {
    asm("fma.rn.f32x2 %0, %1, %2, %0;" : "+l"(d) : "l"(a), "l"(b));
}
__device__ __forceinline__ void upk(ull v, float& lo, float& hi) {
    asm("mov.b64 {%0, %1}, %2;" : "=f"(lo), "=f"(hi) : "l"(v));
}

// ---------------------------------------------------------------------------
// Detect active_mask storage dtype from its byte pattern (first 64KB = the
// smallest candidate buffer size, so always in-bounds). Deterministic.
// ---------------------------------------------------------------------------
__global__ void k_detect(const unsigned char* __restrict__ p) {
    __shared__ int fl[6];
    int t = threadIdx.x;
    if (t < 6) fl[t] = 0;
    __syncthreads();
    int f0 = 0, f1 = 0, f2 = 0, f2x = 0, f3 = 0, f3x = 0;
    const uint4* pu = (const uint4*)p;
    #pragma unroll 4
    for (int k = 0; k < 16; ++k) {
        uint4 q = pu[t * 16 + k];
        unsigned int ws[4] = {q.x, q.y, q.z, q.w};
        #pragma unroll
        for (int j = 0; j < 4; ++j) {
            unsigned int u = ws[j];
            unsigned int b0 = u & 0xFFu, b1 = (u >> 8) & 0xFFu;
            unsigned int b2 = (u >> 16) & 0xFFu, b3 = (u >> 24) & 0xFFu;
            f0 |= (b0 != 0u);
            f1 |= (b1 != 0u);
            f2 |= (b2 != 0u);
            f2x |= (b2 != 0u && b2 != 0x80u);
            f3 |= (b3 != 0u);
            f3x |= (b3 != 0u && b3 != 0x3Fu);
        }
    }
    if (f0)  atomicOr(&fl[0], 1);
    if (f1)  atomicOr(&fl[1], 1);
    if (f2)  atomicOr(&fl[2], 1);
    if (f2x) atomicOr(&fl[3], 1);
    if (f3)  atomicOr(&fl[4], 1);
    if (f3x) atomicOr(&fl[5], 1);
    __syncthreads();
    if (t == 0) {
        int mode;
        if (!fl[1] && !fl[2] && !fl[4])                mode = 1;  // int32 0/1
        else if (!fl[0] && !fl[1] && !fl[3] && !fl[5]) mode = 2;  // float32 0/1
        else                                           mode = 0;  // byte bool
        g_mask_mode = mode;
    }
}

// ---------------------------------------------------------------------------
// g_cn2[c] = 0.5*|codebook[c]|^2 for codes [base, base+256). (warp per code)
// Two launches keep k_main at global launch index 5 for the ncu -s 5 window.
// ---------------------------------------------------------------------------
__global__ void k_cn2(const float* __restrict__ cb, int base) {
    int wid = threadIdx.x >> 5, ln = threadIdx.x & 31;
    int code = base + blockIdx.x * 8 + wid;
    const float4* r = (const float4*)(cb + (size_t)code * DIM);
    float4 a = r[ln], b = r[ln + 32];
    float s = a.x * a.x + a.y * a.y + a.z * a.z + a.w * a.w
            + b.x * b.x + b.y * b.y + b.z * b.z + b.w * b.w;
    #pragma unroll
    for (int off = 16; off; off >>= 1) s += __shfl_xor_sync(0xFFFFFFFFu, s, off);
    if (ln == 0) g_cn2[code] = 0.5f * s;
}

// ---------------------------------------------------------------------------
// Main fused kernel — row-pair FFMA2 microkernel (LDS-traffic-minimized).
// Thread map: ec = t&31 (32 col lanes), rb = t>>5 (warp = 8-row block).
// A-operand (8 rows) comes from 2 broadcast LDS.128 as 4 row-pair ULLs;
// B-operand is a conflict-free scalar LDS + pk2 dup. Phase A: 10 smem
// wavefronts per warp-kk for 32 FFMA2; Phase B: 6 wf for 16 FFMA2.
// Blocks [0,1024): VQ tiles; blocks [1024,1032): C_out = codebook @ W_out^T.
// ---------------------------------------------------------------------------
__global__ void __launch_bounds__(256, 2)
k_main(const float* __restrict__ hidden, const float* __restrict__ codebook,
       const float* __restrict__ Win, const float* __restrict__ Wout)
{
    extern __shared__ float sm[];
    float* zs    = sm + SM_ZS;
    float* Hs    = sm + SM_HS;
    float* Ws    = sm + SM_WS;
    float* Cs    = sm + SM_HS;     // phase-B alias (Hs+Ws dead then)
    float* rowz2 = sm + SM_ROWZ2;
    float* lred  = sm + SM_LRED;

    const int t   = threadIdx.x;
    const int ec  = t & 31;        // column lane
    const int rb  = t >> 5;        // warp id = row block
    const int rb8 = rb << 3;
    const bool isVQ = (blockIdx.x < 1024);

    const float* src;
    const float* Wm;
    int n0;
    if (isVQ) { n0 = blockIdx.x * 64;          src = hidden   + (size_t)n0 * DIM; Wm = Win;  }
    else      { n0 = (blockIdx.x - 1024) * 64; src = codebook + (size_t)n0 * DIM; Wm = Wout; }

    // accA[j][p]: row-pair (rb8+2j, rb8+2j+1) x column e = ec + 32*p
    ull accA[4][8];
    #pragma unroll
    for (int j = 0; j < 4; ++j)
        #pragma unroll
        for (int p = 0; p < 8; ++p) accA[j][p] = 0ull;

    // ---------------- Phase A: z[64][256] = SRC @ Wm^T ----------------
    for (int dk = 0; dk < 8; ++dk) {
        __syncthreads();
        #pragma unroll
        for (int i = 0; i < 2; ++i) {              // Hs: 64 rows x 32 dims, kk-major
            int id = i * 256 + t, r = id >> 3, kg = id & 7;
            float4 v = *(const float4*)(src + (size_t)r * DIM + dk * 32 + kg * 4);
            Hs[(kg * 4 + 0) * 68 + r] = v.x;
            Hs[(kg * 4 + 1) * 68 + r] = v.y;
            Hs[(kg * 4 + 2) * 68 + r] = v.z;
            Hs[(kg * 4 + 3) * 68 + r] = v.w;
        }
        #pragma unroll
        for (int i = 0; i < 8; ++i) {              // Ws: 256 cols x 32 dims, kk-major
            int id = i * 256 + t, e = id >> 3, kg = id & 7;
            float4 v = *(const float4*)(Wm + (size_t)e * DIM + dk * 32 + kg * 4);
            Ws[(kg * 4 + 0) * 258 + e] = v.x;
            Ws[(kg * 4 + 1) * 258 + e] = v.y;
            Ws[(kg * 4 + 2) * 258 + e] = v.z;
            Ws[(kg * 4 + 3) * 258 + e] = v.w;
        }
        __syncthreads();
        #pragma unroll 4
        for (int kk = 0; kk < 32; ++kk) {
            ulonglong2 ha = *(const ulonglong2*)(Hs + kk * 68 + rb8);      // rows 0-3, bcast
            ulonglong2 hb = *(const ulonglong2*)(Hs + kk * 68 + rb8 + 4);  // rows 4-7, bcast
            const float* wr = Ws + kk * 258 + ec;                           // scalar, CF
            #pragma unroll
            for (int p = 0; p < 8; ++p) {
                ull wp = pk2(wr[32 * p]);
                fma2(accA[0][p], ha.x, wp);
                fma2(accA[1][p], ha.y, wp);
                fma2(accA[2][p], hb.x, wp);
                fma2(accA[3][p], hb.y, wp);
            }
        }
    }

    if (!isVQ) {  // C_out blocks: store and exit
        #pragma unroll
        for (int p = 0; p < 8; ++p) {
            int e = ec + 32 * p;
            #pragma unroll
            for (int j = 0; j < 4; ++j) {
                float lo, hi; upk(accA[j][p], lo, hi);
                g_cout[(size_t)(n0 + rb8 + 2 * j    ) * DIM + e] = lo;
                g_cout[(size_t)(n0 + rb8 + 2 * j + 1) * DIM + e] = hi;
            }
        }
        return;
    }

    // transpose-write z to smem (dim-major, stride 68): row-pairs -> float2 STS
    #pragma unroll
    for (int p = 0; p < 8; ++p) {
        int e = ec + 32 * p;
        #pragma unroll
        for (int j = 0; j < 4; ++j) {
            float lo, hi; upk(accA[j][p], lo, hi);
            *(float2*)(zs + e * 68 + rb8 + 2 * j) = make_float2(lo, hi);
        }
    }
    __syncthreads();

    // rowz2[r] = |z_r|^2  (4 threads per row, fixed-order reduce)
    {
        int row = t >> 2, part = t & 3;
        float s = 0.0f;
        #pragma unroll 8
        for (int j = 0; j < 64; ++j) {
            float v = zs[(part * 64 + j) * 68 + row];
            s = fmaf(v, v, s);
        }
        s += __shfl_xor_sync(0xFFFFFFFFu, s, 1);
        s += __shfl_xor_sync(0xFFFFFFFFu, s, 2);
        if (part == 0) rowz2[row] = s;
    }

    // -------- Phase B: score 512 codes; 32 flat stages, reg-prefetch --------
    float best[8];
    int   bidx[8];
    #pragma unroll
    for (int i = 0; i < 8; ++i) { best[i] = -3.0e38f; bidx[i] = 0; }

    const int sid = t >> 3;        // staging: code within chunk
    const int skg = t & 7;         // staging: dim group

    float4 pf[4];
    #pragma unroll
    for (int i = 0; i < 4; ++i) {  // prefetch stage 0 (ch=0, dk=0)
        int c = i * 32 + sid;
        pf[i] = *(const float4*)(codebook + (size_t)c * DIM + skg * 4);
    }

    // acc2[j][p]: row-pair (rb8+2j, +1) x code e = ec + 32*p within chunk
    ull acc2[4][4];

    for (int s = 0; s < 32; ++s) {
        const int dk = s & 7;
        const int c0 = (s >> 3) * 128;

        if (dk == 0) {
            #pragma unroll
            for (int j = 0; j < 4; ++j)
                #pragma unroll
                for (int p = 0; p < 4; ++p) acc2[j][p] = 0ull;
        }

        __syncthreads();                           // prev stage consumers done
        #pragma unroll
        for (int i = 0; i < 4; ++i) {              // Cs: 128 codes x 32 dims, kk-major
            int c = i * 32 + sid;
            Cs[(skg * 4 + 0) * 130 + c] = pf[i].x;
            Cs[(skg * 4 + 1) * 130 + c] = pf[i].y;
            Cs[(skg * 4 + 2) * 130 + c] = pf[i].z;
            Cs[(skg * 4 + 3) * 130 + c] = pf[i].w;
        }
        __syncthreads();                           // Cs ready

        if (s + 1 < 32) {                          // prefetch next stage
            int c0n = ((s + 1) >> 3) * 128;
            int dkn = (s + 1) & 7;
            #pragma unroll
            for (int i = 0; i < 4; ++i) {
                int c = i * 32 + sid;
                pf[i] = *(const float4*)(codebook + (size_t)(c0n + c) * DIM + dkn * 32 + skg * 4);
            }
        }

        #pragma unroll 4
        for (int kk = 0; kk < 32; ++kk) {
            const float* zb = zs + (dk * 32 + kk) * 68 + rb8;
            ulonglong2 za = *(const ulonglong2*)(zb);       // rows 0-3, bcast
            ulonglong2 zc = *(const ulonglong2*)(zb + 4);   // rows 4-7, bcast
            const float* cr = Cs + kk * 130 + ec;            // scalar, CF
            #pragma unroll
            for (int p = 0; p < 4; ++p) {
                ull cp = pk2(cr[32 * p]);
                fma2(acc2[0][p], za.x, cp);
                fma2(acc2[1][p], za.y, cp);
                fma2(acc2[2][p], zc.x, cp);
                fma2(acc2[3][p], zc.y, cp);
            }
        }

        if (dk == 7) {
            #pragma unroll
            for (int p = 0; p < 4; ++p) {
                int c = c0 + ec + 32 * p;
                float hc = g_cn2[c];
                #pragma unroll
                for (int j = 0; j < 4; ++j) {
                    float lo, hi; upk(acc2[j][p], lo, hi);
                    float s0 = lo - hc;                 // z.c - 0.5|c|^2
                    float s1 = hi - hc;
                    int i0 = 2 * j, i1 = 2 * j + 1;
                    if (s0 > best[i0] || (s0 == best[i0] && c < bidx[i0])) { best[i0] = s0; bidx[i0] = c; }
                    if (s1 > best[i1] || (s1 == best[i1] && c < bidx[i1])) { best[i1] = s1; bidx[i1] = c; }
                }
            }
        }
    }

    // full-warp argmax reduce across ec; lower index wins ties
    #pragma unroll
    for (int i = 0; i < 8; ++i) {
        float s = best[i]; int ix = bidx[i];
        #pragma unroll
        for (int off = 16; off; off >>= 1) {
            float so = __shfl_down_sync(0xFFFFFFFFu, s, off);
            int   io = __shfl_down_sync(0xFFFFFFFFu, ix, off);
            if (so > s || (so == s && io < ix)) { s = so; ix = io; }
        }
        best[i] = s; bidx[i] = ix;
    }

    if (ec == 0) {
        float lsum = 0.0f;
        #pragma unroll
        for (int i = 0; i < 8; ++i) {
            int row = rb8 + i;
            g_idx[n0 + row] = bidx[i];
            lsum += rowz2[row] - 2.0f * best[i];   // |z - c*|^2 for the row
        }
        lred[rb] = lsum;
    }
    __syncthreads();
    if (t == 0) {
        float s = 0.0f;
        #pragma unroll
        for (int j = 0; j < 8; ++j) s += lred[j];   // fixed order -> deterministic
        g_partial[blockIdx.x] = s;
    }
}

// ---------------------------------------------------------------------------
// Epilogue: blocks [0,8192): h = hidden + mask*C_out[idx]; LayerNorm (warp/row).
// Block 8192: vq_loss = 1.25 * sum(g_partial) / (N*D), deterministic tree.
// ---------------------------------------------------------------------------
__global__ void __launch_bounds__(256)
k_pass2(const float* __restrict__ hidden, const void* __restrict__ maskp,
        const float* __restrict__ gamma, const float* __restrict__ beta,
        float* __restrict__ out, int has_loss)
{
    if (blockIdx.x == 8192) {                       // loss block
        __shared__ float red[256];
        int t = threadIdx.x;
        float s = g_partial[t] + g_partial[t + 256] + g_partial[t + 512] + g_partial[t + 768];
        red[t] = s;
        __syncthreads();
        for (int off = 128; off; off >>= 1) {
            if (t < off) red[t] += red[t + off];
            __syncthreads();
        }
        if (t == 0 && has_loss) out[ND] = 1.25f * red[0] / (float)ND;
        return;
    }

    int w = threadIdx.x >> 5, ln = threadIdx.x & 31;
    int n = blockIdx.x * 8 + w;
    int code = g_idx[n];
    int mode = g_mask_mode;
    float m;
    if (mode == 1)      m = ((const int*)maskp)[n] ? 1.0f : 0.0f;
    else if (mode == 2) m = ((const float*)maskp)[n];
    else                m = ((const unsigned char*)maskp)[n] ? 1.0f : 0.0f;

    const float4* hr = (const float4*)(hidden + (size_t)n * DIM);
    const float4* cr = (const float4*)(g_cout + (size_t)code * DIM);
    float4 h0 = hr[ln],      h1 = hr[ln + 32];
    float4 c0 = cr[ln],      c1 = cr[ln + 32];
    h0.x = fmaf(m, c0.x, h0.x); h0.y = fmaf(m, c0.y, h0.y);
    h0.z = fmaf(m, c0.z, h0.z); h0.w = fmaf(m, c0.w, h0.w);
    h1.x = fmaf(m, c1.x, h1.x); h1.y = fmaf(m, c1.y, h1.y);
    h1.z = fmaf(m, c1.z, h1.z); h1.w = fmaf(m, c1.w, h1.w);

    float sum = h0.x + h0.y + h0.z + h0.w + h1.x + h1.y + h1.z + h1.w;
    #pragma unroll
    for (int off = 16; off; off >>= 1) sum += __shfl_xor_sync(0xFFFFFFFFu, sum, off);
    float mu = sum * (1.0f / 256.0f);

    float d0 = h0.x - mu, d1 = h0.y - mu, d2 = h0.z - mu, d3 = h0.w - mu;
    float d4 = h1.x - mu, d5 = h1.y - mu, d6 = h1.z - mu, d7 = h1.w - mu;
    float vs = d0*d0 + d1*d1 + d2*d2 + d3*d3 + d4*d4 + d5*d5 + d6*d6 + d7*d7;
    #pragma unroll
    for (int off = 16; off; off >>= 1) vs += __shfl_xor_sync(0xFFFFFFFFu, vs, off);
    float inv = rsqrtf(vs * (1.0f / 256.0f) + 1e-5f);

    float4 g0 = ((const float4*)gamma)[ln], g1 = ((const float4*)gamma)[ln + 32];
    float4 b0 = ((const float4*)beta)[ln],  b1 = ((const float4*)beta)[ln + 32];
    float4 o0 = make_float4(fmaf(d0 * inv, g0.x, b0.x), fmaf(d1 * inv, g0.y, b0.y),
                            fmaf(d2 * inv, g0.z, b0.z), fmaf(d3 * inv, g0.w, b0.w));
    float4 o1 = make_float4(fmaf(d4 * inv, g1.x, b1.x), fmaf(d5 * inv, g1.y, b1.y),
                            fmaf(d6 * inv, g1.z, b1.z), fmaf(d7 * inv, g1.w, b1.w));
    float4* orow = (float4*)(out + (size_t)n * DIM);
    orow[ln]      = o0;
    orow[ln + 32] = o1;
}

// ---------------------------------------------------------------------------
extern "C" void kernel_launch(void* const* d_in, const int* in_sizes, int n_in,
                              void* d_out, int out_size) {
    const float* hidden   = (const float*)d_in[0];
    const void*  mask     = d_in[1];
    const float* codebook = (const float*)d_in[2];
    const float* Win      = (const float*)d_in[3];
    const float* Wout     = (const float*)d_in[4];
    const float* gamma    = (const float*)d_in[5];
    const float* beta     = (const float*)d_in[6];
    float* out = (float*)d_out;

    cudaFuncSetAttribute(k_main, cudaFuncAttributeMaxDynamicSharedMemorySize, SM_BYTES);

    k_detect<<<1, 256>>>((const unsigned char*)mask);
    k_cn2<<<32, 256>>>(codebook, 0);
    k_cn2<<<32, 256>>>(codebook, 256);
    k_main<<<1032, 256, SM_BYTES>>>(hidden, codebook, Win, Wout);
    k_pass2<<<8193, 256>>>(hidden, mask, gamma, beta, out, (out_size > ND) ? 1 : 0);
}

// round 13
// speedup vs baseline: 1.3502x; 1.3502x over previous
#include <cuda_runtime.h>
#include <cuda_bf16.h>
#include <cstdint>

#define N_ROWS   65536
#define DIM      256
#define NCODES   512
#define ND       16777216       // N_ROWS*DIM

typedef unsigned long long ull;

// ---------------- device scratch (no allocations allowed) ----------------
__device__ int      g_idx[N_ROWS];
__device__ float    g_cn2[NCODES];             // 0.5*|c|^2 (fp32 exact)
__device__ float    g_cout[NCODES * DIM];      // codebook @ W_out^T (fp32)
__device__ float    g_rowz2[N_ROWS];           // |z_row|^2 (fp32 exact)
__device__ float    g_partial[512];            // per-tile loss partials
__device__ int      g_mask_mode;
__device__ uint32_t g_zhi[N_ROWS * 128];       // z hi bf16x2 (dims 2j,2j+1)
__device__ uint32_t g_zlo[N_ROWS * 128];       // z residual bf16x2
__device__ uint32_t g_cbhi[NCODES * 128];      // codebook hi bf16x2
__device__ uint32_t g_cblo[NCODES * 128];      // codebook residual bf16x2

// ---- packed fp32x2 helpers (k_gemm fp32 microkernel) ----
__device__ __forceinline__ ull pk2(float f) {
    ull d; asm("mov.b64 %0, {%1, %1};" : "=l"(d) : "f"(f)); return d;
}
__device__ __forceinline__ void fma2(ull& d, ull a, ull b) {
    asm("fma.rn.f32x2 %0, %1, %2, %0;" : "+l"(d) : "l"(a), "l"(b));
}
__device__ __forceinline__ void upk(ull v, float& lo, float& hi) {
    asm("mov.b64 {%0, %1}, %2;" : "=f"(lo), "=f"(hi) : "l"(v));
}
__device__ __forceinline__ uint32_t bf2u(__nv_bfloat162 b) {
    union { __nv_bfloat162 b; uint32_t u; } c; c.b = b; return c.u;
}
__device__ __forceinline__ uint32_t smem_to_u32(const void* p) {
    uint32_t a;
    asm("{ .reg .u64 t; cvta.to.shared.u64 t, %1; cvt.u32.u64 %0, t; }"
        : "=r"(a) : "l"(p));
    return a;
}

// ---------------------------------------------------------------------------
// Detect active_mask storage dtype (first 64KB). Deterministic.
// ---------------------------------------------------------------------------
__global__ void k_detect(const unsigned char* __restrict__ p) {
    __shared__ int fl[6];
    int t = threadIdx.x;
    if (t < 6) fl[t] = 0;
    __syncthreads();
    int f0 = 0, f1 = 0, f2 = 0, f2x = 0, f3 = 0, f3x = 0;
    const uint4* pu = (const uint4*)p;
    #pragma unroll 4
    for (int k = 0; k < 16; ++k) {
        uint4 q = pu[t * 16 + k];
        unsigned int ws[4] = {q.x, q.y, q.z, q.w};
        #pragma unroll
        for (int j = 0; j < 4; ++j) {
            unsigned int u = ws[j];
            unsigned int b0 = u & 0xFFu, b1 = (u >> 8) & 0xFFu;
            unsigned int b2 = (u >> 16) & 0xFFu, b3 = (u >> 24) & 0xFFu;
            f0 |= (b0 != 0u); f1 |= (b1 != 0u); f2 |= (b2 != 0u);
            f2x |= (b2 != 0u && b2 != 0x80u);
            f3 |= (b3 != 0u);
            f3x |= (b3 != 0u && b3 != 0x3Fu);
        }
    }
    if (f0)  atomicOr(&fl[0], 1);
    if (f1)  atomicOr(&fl[1], 1);
    if (f2)  atomicOr(&fl[2], 1);
    if (f2x) atomicOr(&fl[3], 1);
    if (f3)  atomicOr(&fl[4], 1);
    if (f3x) atomicOr(&fl[5], 1);
    __syncthreads();
    if (t == 0) {
        int mode;
        if (!fl[1] && !fl[2] && !fl[4])                mode = 1;
        else if (!fl[0] && !fl[1] && !fl[3] && !fl[5]) mode = 2;
        else                                           mode = 0;
        g_mask_mode = mode;
    }
}

// ---------------------------------------------------------------------------
// k_cb: per code — cn2 (fp32) + bf16 hi/lo split of the codebook.
// ---------------------------------------------------------------------------
__global__ void k_cb(const float* __restrict__ cb) {
    int wid = threadIdx.x >> 5, ln = threadIdx.x & 31;
    int code = blockIdx.x * 8 + wid;
    const float4* r = (const float4*)(cb + (size_t)code * DIM);
    float4 a = r[ln], b = r[ln + 32];
    float s = a.x * a.x + a.y * a.y + a.z * a.z + a.w * a.w
            + b.x * b.x + b.y * b.y + b.z * b.z + b.w * b.w;
    #pragma unroll
    for (int off = 16; off; off >>= 1) s += __shfl_xor_sync(0xFFFFFFFFu, s, off);
    if (ln == 0) g_cn2[code] = 0.5f * s;

    size_t base = (size_t)code * 128;
    float v0[8] = {a.x, a.y, a.z, a.w, b.x, b.y, b.z, b.w};
    int idxs[4] = {2 * ln, 2 * ln + 1, 64 + 2 * ln, 64 + 2 * ln + 1};
    #pragma unroll
    for (int q = 0; q < 4; ++q) {
        float x = v0[2 * q], y = v0[2 * q + 1];
        __nv_bfloat162 hb = __floats2bfloat162_rn(x, y);
        float rx = x - __bfloat162float(hb.x);
        float ry = y - __bfloat162float(hb.y);
        __nv_bfloat162 lb = __floats2bfloat162_rn(rx, ry);
        g_cbhi[base + idxs[q]] = bf2u(hb);
        g_cblo[base + idxs[q]] = bf2u(lb);
    }
}

// ---------------------------------------------------------------------------
// k_gemm — the measured-best fp32 FFMA2 microkernel (round-4), standalone.
// Blocks [0,1024): z tile 64x256 -> rowz2 (fp32) + bf16 hi/lo z to global.
// Blocks [1024,1032): C_out = codebook @ W_out^T (fp32 to g_cout).
// ---------------------------------------------------------------------------
#define G_SM_HS 0
#define G_SM_WS 2176
#define G_SM_FLOATS (2176 + 8256)
#define G_SM_BYTES  (G_SM_FLOATS * 4)

__global__ void __launch_bounds__(256, 2)
k_gemm(const float* __restrict__ hidden, const float* __restrict__ codebook,
       const float* __restrict__ Win, const float* __restrict__ Wout)
{
    extern __shared__ float sm[];
    float* Hs = sm + G_SM_HS;
    float* Ws = sm + G_SM_WS;

    const int t   = threadIdx.x;
    const int rb  = t >> 4;
    const int ec  = t & 15;
    const int rb4 = rb << 2;
    const bool isVQ = (blockIdx.x < 1024);

    const float* src;
    const float* Wm;
    int n0;
    if (isVQ) { n0 = blockIdx.x * 64;          src = hidden   + (size_t)n0 * DIM; Wm = Win;  }
    else      { n0 = (blockIdx.x - 1024) * 64; src = codebook + (size_t)n0 * DIM; Wm = Wout; }

    ull accA[4][8];
    #pragma unroll
    for (int i = 0; i < 4; ++i)
        #pragma unroll
        for (int p = 0; p < 8; ++p) accA[i][p] = 0ull;

    for (int dk = 0; dk < 8; ++dk) {
        __syncthreads();
        #pragma unroll
        for (int i = 0; i < 2; ++i) {              // Hs: 64 rows x 32 dims, kk-major
            int id = i * 256 + t, r = id >> 3, kg = id & 7;
            float4 v = *(const float4*)(src + (size_t)r * DIM + dk * 32 + kg * 4);
            Hs[(kg * 4 + 0) * 68 + r] = v.x;
            Hs[(kg * 4 + 1) * 68 + r] = v.y;
            Hs[(kg * 4 + 2) * 68 + r] = v.z;
            Hs[(kg * 4 + 3) * 68 + r] = v.w;
        }
        #pragma unroll
        for (int i = 0; i < 8; ++i) {              // Ws: 256 cols x 32 dims, kk-major
            int id = i * 256 + t, e = id >> 3, kg = id & 7;
            float4 v = *(const float4*)(Wm + (size_t)e * DIM + dk * 32 + kg * 4);
            Ws[(kg * 4 + 0) * 258 + e] = v.x;
            Ws[(kg * 4 + 1) * 258 + e] = v.y;
            Ws[(kg * 4 + 2) * 258 + e] = v.z;
            Ws[(kg * 4 + 3) * 258 + e] = v.w;
        }
        __syncthreads();
        #pragma unroll 4
        for (int kk = 0; kk < 32; ++kk) {
            float4 h4 = *(const float4*)(Hs + kk * 68 + rb4);   // broadcast
            ull hz0 = pk2(h4.x), hz1 = pk2(h4.y), hz2 = pk2(h4.z), hz3 = pk2(h4.w);
            const float* wr = Ws + kk * 258 + 2 * ec;           // LDS.64, CF
            #pragma unroll
            for (int p = 0; p < 8; ++p) {
                ull wp = *(const ull*)(wr + 32 * p);
                fma2(accA[0][p], hz0, wp);
                fma2(accA[1][p], hz1, wp);
                fma2(accA[2][p], hz2, wp);
                fma2(accA[3][p], hz3, wp);
            }
        }
    }

    if (!isVQ) {  // C_out blocks
        #pragma unroll
        for (int p = 0; p < 8; ++p) {
            int e = 2 * ec + 32 * p;
            #pragma unroll
            for (int i = 0; i < 4; ++i) {
                float lo, hi; upk(accA[i][p], lo, hi);
                *(float2*)(g_cout + (size_t)(n0 + rb4 + i) * DIM + e) = make_float2(lo, hi);
            }
        }
        return;
    }

    // rowz2 from fp32 accs (fixed order, width-16 shfl across ec)
    float pz[4] = {0.f, 0.f, 0.f, 0.f};
    #pragma unroll
    for (int p = 0; p < 8; ++p)
        #pragma unroll
        for (int i = 0; i < 4; ++i) {
            float lo, hi; upk(accA[i][p], lo, hi);
            pz[i] = fmaf(lo, lo, pz[i]);
            pz[i] = fmaf(hi, hi, pz[i]);
        }
    #pragma unroll
    for (int i = 0; i < 4; ++i) {
        #pragma unroll
        for (int off = 8; off; off >>= 1)
            pz[i] += __shfl_down_sync(0xFFFFFFFFu, pz[i], off, 16);
    }
    if (ec == 0) {
        #pragma unroll
        for (int i = 0; i < 4; ++i) g_rowz2[n0 + rb4 + i] = pz[i];
    }

    // bf16 hi/lo split of z to global (pair cols 2ec+32p,+1 -> u32 idx ec+16p)
    #pragma unroll
    for (int p = 0; p < 8; ++p) {
        int ci = ec + 16 * p;
        #pragma unroll
        for (int i = 0; i < 4; ++i) {
            float lo, hi; upk(accA[i][p], lo, hi);
            __nv_bfloat162 hb = __floats2bfloat162_rn(lo, hi);
            float rl = lo - __bfloat162float(hb.x);
            float rh = hi - __bfloat162float(hb.y);
            __nv_bfloat162 lb = __floats2bfloat162_rn(rl, rh);
            size_t idx = (size_t)(n0 + rb4 + i) * 128 + ci;
            g_zhi[idx] = bf2u(hb);
            g_zlo[idx] = bf2u(lb);
        }
    }
}

// ---------------------------------------------------------------------------
// k_score — bf16 3-split scoring via mma.sync (HMMA; arch-neutral PTX).
// CTA = 128 rows x 512 codes; warp = 16 rows x 128-code chunk (64 f32 accs).
// K = 12 slices of 64 dims: kc 0-3 zh*ch, 4-7 zl*ch, 8-11 zh*cl; fp32 accum.
// smem: As 128x72 bf16 (stride 144B, LDSM conflict-free), Bs 128x72 bf16.
// score = D - 0.5|c|^2; in-register argmax; quad-lane reduce; fixed-order loss.
// ---------------------------------------------------------------------------
__global__ void __launch_bounds__(256, 2)
k_score()
{
    __shared__ __align__(16) unsigned char As[18432];  // 128 x 72 bf16
    __shared__ __align__(16) unsigned char Bs[18432];  // 128 x 72 bf16
    __shared__ float cn2s[128];
    __shared__ float red[128];

    const int tid  = threadIdx.x;
    const int wid  = tid >> 5;
    const int lane = tid & 31;
    const int wr   = wid * 16;
    const int rowg = blockIdx.x * 128;
    const uint32_t As_b = smem_to_u32(As);
    const uint32_t Bs_b = smem_to_u32(Bs);

    // ldmatrix lane addressing (A x4: r=lane&15, k-half=lane&16; B x2: lanes 0-15)
    const uint32_t a_row  = (uint32_t)(wr + (lane & 15));
    const uint32_t a_koff = (lane & 16) ? 16u : 0u;          // bytes
    const uint32_t b_row  = (uint32_t)(lane & 7);
    const uint32_t b_koff = ((lane >> 3) & 1) ? 16u : 0u;    // bytes

    float best0 = -3.0e38f, best1 = -3.0e38f;
    int   bi0 = 0, bi1 = 0;

    for (int chunk = 0; chunk < 4; ++chunk) {
        __syncthreads();                       // prev-chunk cn2s readers done
        float acc[16][4];
        #pragma unroll
        for (int j = 0; j < 16; ++j) {
            acc[j][0] = 0.f; acc[j][1] = 0.f; acc[j][2] = 0.f; acc[j][3] = 0.f;
        }
        if (tid < 128) cn2s[tid] = g_cn2[chunk * 128 + tid];

        for (int kc = 0; kc < 12; ++kc) {
            const int seg = kc >> 2, k64 = kc & 3;
            const uint32_t* Asrc = (seg == 1) ? g_zlo : g_zhi;
            const uint32_t* Bsrc = (seg == 2) ? g_cblo : g_cbhi;
            __syncthreads();                   // prev slice consumers done
            #pragma unroll
            for (int it = 0; it < 16; ++it) {  // 4096 u32 each for A and B
                int idx = it * 256 + tid;
                int row = idx >> 5, jc = idx & 31;
                ((uint32_t*)As)[row * 36 + jc] =
                    Asrc[(size_t)(rowg + row) * 128 + k64 * 32 + jc];
                ((uint32_t*)Bs)[row * 36 + jc] =
                    Bsrc[(size_t)(chunk * 128 + row) * 128 + k64 * 32 + jc];
            }
            __syncthreads();

            #pragma unroll
            for (int k8 = 0; k8 < 4; ++k8) {
                uint32_t a0, a1, a2, a3;
                uint32_t aaddr = As_b + a_row * 144u + (uint32_t)k8 * 32u + a_koff;
                asm volatile(
                    "ldmatrix.sync.aligned.m8n8.x4.shared.b16 {%0,%1,%2,%3}, [%4];"
                    : "=r"(a0), "=r"(a1), "=r"(a2), "=r"(a3) : "r"(aaddr));
                #pragma unroll
                for (int j = 0; j < 16; ++j) {
                    uint32_t b0, b1;
                    uint32_t baddr = Bs_b + (uint32_t)(j * 8 + b_row) * 144u
                                   + (uint32_t)k8 * 32u + b_koff;
                    asm volatile(
                        "ldmatrix.sync.aligned.m8n8.x2.shared.b16 {%0,%1}, [%2];"
                        : "=r"(b0), "=r"(b1) : "r"(baddr));
                    asm volatile(
                        "mma.sync.aligned.m16n8k16.row.col.f32.bf16.bf16.f32 "
                        "{%0,%1,%2,%3}, {%4,%5,%6,%7}, {%8,%9}, {%0,%1,%2,%3};"
                        : "+f"(acc[j][0]), "+f"(acc[j][1]),
                          "+f"(acc[j][2]), "+f"(acc[j][3])
                        : "r"(a0), "r"(a1), "r"(a2), "r"(a3), "r"(b0), "r"(b1));
                }
            }
        }

        // extraction: lane holds rows (wr+lane/4, +8), codes j*8+(lane%4)*2,+1
        #pragma unroll
        for (int j = 0; j < 16; ++j) {
            int cl = j * 8 + ((lane & 3) << 1);
            float h0 = cn2s[cl], h1 = cn2s[cl + 1];
            int code = chunk * 128 + cl;
            float s00 = acc[j][0] - h0, s01 = acc[j][1] - h1;
            float s10 = acc[j][2] - h0, s11 = acc[j][3] - h1;
            if (s00 > best0 || (s00 == best0 && code     < bi0)) { best0 = s00; bi0 = code;     }
            if (s01 > best0 || (s01 == best0 && code + 1 < bi0)) { best0 = s01; bi0 = code + 1; }
            if (s10 > best1 || (s10 == best1 && code     < bi1)) { best1 = s10; bi1 = code;     }
            if (s11 > best1 || (s11 == best1 && code + 1 < bi1)) { best1 = s11; bi1 = code + 1; }
        }
    }

    // reduce across the 4 lanes sharing l/4 (disjoint code subsets per lane)
    #pragma unroll
    for (int off = 1; off <= 2; off <<= 1) {
        float s = __shfl_xor_sync(0xFFFFFFFFu, best0, off);
        int   i = __shfl_xor_sync(0xFFFFFFFFu, bi0,   off);
        if (s > best0 || (s == best0 && i < bi0)) { best0 = s; bi0 = i; }
        s = __shfl_xor_sync(0xFFFFFFFFu, best1, off);
        i = __shfl_xor_sync(0xFFFFFFFFu, bi1,   off);
        if (s > best1 || (s == best1 && i < bi1)) { best1 = s; bi1 = i; }
    }
    if ((lane & 3) == 0) {
        int r0 = wr + (lane >> 2);
        int r1 = r0 + 8;
        g_idx[rowg + r0] = bi0;
        g_idx[rowg + r1] = bi1;
        red[r0] = g_rowz2[rowg + r0] - 2.0f * best0;   // |z - c*|^2
        red[r1] = g_rowz2[rowg + r1] - 2.0f * best1;
    }
    __syncthreads();
    if (tid == 0) {
        float s = 0.0f;
        for (int j = 0; j < 128; ++j) s += red[j];     // fixed order
        g_partial[blockIdx.x] = s;
    }
}

// ---------------------------------------------------------------------------
// Epilogue: blocks [0,8192): h = hidden + mask*C_out[idx]; LayerNorm (warp/row).
// Block 8192: vq_loss = 1.25 * sum(g_partial[0..511]) / (N*D).
// ---------------------------------------------------------------------------
__global__ void __launch_bounds__(256)
k_pass2(const float* __restrict__ hidden, const void* __restrict__ maskp,
        const float* __restrict__ gamma, const float* __restrict__ beta,
        float* __restrict__ out, int has_loss)
{
    if (blockIdx.x == 8192) {
        __shared__ float red[256];
        int t = threadIdx.x;
        red[t] = g_partial[t] + g_partial[t + 256];
        __syncthreads();
        for (int off = 128; off; off >>= 1) {
            if (t < off) red[t] += red[t + off];
            __syncthreads();
        }
        if (t == 0 && has_loss) out[ND] = 1.25f * red[0] / (float)ND;
        return;
    }

    int w = threadIdx.x >> 5, ln = threadIdx.x & 31;
    int n = blockIdx.x * 8 + w;
    int code = g_idx[n];
    int mode = g_mask_mode;
    float m;
    if (mode == 1)      m = ((const int*)maskp)[n] ? 1.0f : 0.0f;
    else if (mode == 2) m = ((const float*)maskp)[n];
    else                m = ((const unsigned char*)maskp)[n] ? 1.0f : 0.0f;

    const float4* hr = (const float4*)(hidden + (size_t)n * DIM);
    const float4* cr = (const float4*)(g_cout + (size_t)code * DIM);
    float4 h0 = hr[ln],      h1 = hr[ln + 32];
    float4 c0 = cr[ln],      c1 = cr[ln + 32];
    h0.x = fmaf(m, c0.x, h0.x); h0.y = fmaf(m, c0.y, h0.y);
    h0.z = fmaf(m, c0.z, h0.z); h0.w = fmaf(m, c0.w, h0.w);
    h1.x = fmaf(m, c1.x, h1.x); h1.y = fmaf(m, c1.y, h1.y);
    h1.z = fmaf(m, c1.z, h1.z); h1.w = fmaf(m, c1.w, h1.w);

    float sum = h0.x + h0.y + h0.z + h0.w + h1.x + h1.y + h1.z + h1.w;
    #pragma unroll
    for (int off = 16; off; off >>= 1) sum += __shfl_xor_sync(0xFFFFFFFFu, sum, off);
    float mu = sum * (1.0f / 256.0f);

    float d0 = h0.x - mu, d1 = h0.y - mu, d2 = h0.z - mu, d3 = h0.w - mu;
    float d4 = h1.x - mu, d5 = h1.y - mu, d6 = h1.z - mu, d7 = h1.w - mu;
    float vs = d0*d0 + d1*d1 + d2*d2 + d3*d3 + d4*d4 + d5*d5 + d6*d6 + d7*d7;
    #pragma unroll
    for (int off = 16; off; off >>= 1) vs += __shfl_xor_sync(0xFFFFFFFFu, vs, off);
    float inv = rsqrtf(vs * (1.0f / 256.0f) + 1e-5f);

    float4 g0 = ((const float4*)gamma)[ln], g1 = ((const float4*)gamma)[ln + 32];
    float4 b0 = ((const float4*)beta)[ln],  b1 = ((const float4*)beta)[ln + 32];
    float4 o0 = make_float4(fmaf(d0 * inv, g0.x, b0.x), fmaf(d1 * inv, g0.y, b0.y),
                            fmaf(d2 * inv, g0.z, b0.z), fmaf(d3 * inv, g0.w, b0.w));
    float4 o1 = make_float4(fmaf(d4 * inv, g1.x, b1.x), fmaf(d5 * inv, g1.y, b1.y),
                            fmaf(d6 * inv, g1.z, b1.z), fmaf(d7 * inv, g1.w, b1.w));
    float4* orow = (float4*)(out + (size_t)n * DIM);
    orow[ln]      = o0;
    orow[ln + 32] = o1;
}

// ---------------------------------------------------------------------------
extern "C" void kernel_launch(void* const* d_in, const int* in_sizes, int n_in,
                              void* d_out, int out_size) {
    const float* hidden   = (const float*)d_in[0];
    const void*  mask     = d_in[1];
    const float* codebook = (const float*)d_in[2];
    const float* Win      = (const float*)d_in[3];
    const float* Wout     = (const float*)d_in[4];
    const float* gamma    = (const float*)d_in[5];
    const float* beta     = (const float*)d_in[6];
    float* out = (float*)d_out;

    // global launch indices (harness emits 2 first): detect=2, cb=3, gemm=4,
    // score=5 (ncu -s 5 capture target), pass2=6.
    k_detect<<<1, 256>>>((const unsigned char*)mask);
    k_cb<<<64, 256>>>(codebook);
    k_gemm<<<1032, 256, G_SM_BYTES>>>(hidden, codebook, Win, Wout);
    k_score<<<512, 256>>>();
    k_pass2<<<8193, 256>>>(hidden, mask, gamma, beta, out, (out_size > ND) ? 1 : 0);
}

// round 16
// speedup vs baseline: 1.5552x; 1.1519x over previous
#include <cuda_runtime.h>
#include <cuda_bf16.h>
#include <cstdint>

#define N_ROWS   65536
#define DIM      256
#define NCODES   512
#define ND       16777216       // N_ROWS*DIM

typedef unsigned long long ull;

// ---------------- device scratch (no allocations allowed) ----------------
__device__ int      g_idx[N_ROWS];
__device__ float    g_cn2[NCODES];             // 0.5*|c|^2 (fp32 exact)
__device__ float    g_cout[NCODES * DIM];      // codebook @ W_out^T (fp32)
__device__ float    g_rowz2[N_ROWS];           // |z_row|^2 (fp32 exact)
__device__ float    g_partial[512];            // per-tile loss partials
__device__ int      g_mask_mode;
__device__ uint32_t g_zhi[N_ROWS * 128];       // z hi bf16x2 (dims 2j,2j+1)
__device__ uint32_t g_zlo[N_ROWS * 128];       // z residual bf16x2
__device__ uint32_t g_cbhi[NCODES * 128];      // codebook hi bf16x2
__device__ uint32_t g_cblo[NCODES * 128];      // codebook residual bf16x2

// ---- packed fp32x2 helpers (k_gemm fp32 microkernel) ----
__device__ __forceinline__ ull pk2(float f) {
    ull d; asm("mov.b64 %0, {%1, %1};" : "=l"(d) : "f"(f)); return d;
}
__device__ __forceinline__ void fma2(ull& d, ull a, ull b) {
    asm("fma.rn.f32x2 %0, %1, %2, %0;" : "+l"(d) : "l"(a), "l"(b));
}
__device__ __forceinline__ void upk(ull v, float& lo, float& hi) {
    asm("mov.b64 {%0, %1}, %2;" : "=f"(lo), "=f"(hi) : "l"(v));
}
__device__ __forceinline__ uint32_t bf2u(__nv_bfloat162 b) {
    union { __nv_bfloat162 b; uint32_t u; } c; c.b = b; return c.u;
}
__device__ __forceinline__ uint32_t smem_to_u32(const void* p) {
    uint32_t a;
    asm("{ .reg .u64 t; cvta.to.shared.u64 t, %1; cvt.u32.u64 %0, t; }"
        : "=r"(a) : "l"(p));
    return a;
}

// ---------------------------------------------------------------------------
// Detect active_mask storage dtype (first 64KB). Deterministic.
// ---------------------------------------------------------------------------
__global__ void k_detect(const unsigned char* __restrict__ p) {
    __shared__ int fl[6];
    int t = threadIdx.x;
    if (t < 6) fl[t] = 0;
    __syncthreads();
    int f0 = 0, f1 = 0, f2 = 0, f2x = 0, f3 = 0, f3x = 0;
    const uint4* pu = (const uint4*)p;
    #pragma unroll 4
    for (int k = 0; k < 16; ++k) {
        uint4 q = pu[t * 16 + k];
        unsigned int ws[4] = {q.x, q.y, q.z, q.w};
        #pragma unroll
        for (int j = 0; j < 4; ++j) {
            unsigned int u = ws[j];
            unsigned int b0 = u & 0xFFu, b1 = (u >> 8) & 0xFFu;
            unsigned int b2 = (u >> 16) & 0xFFu, b3 = (u >> 24) & 0xFFu;
            f0 |= (b0 != 0u); f1 |= (b1 != 0u); f2 |= (b2 != 0u);
            f2x |= (b2 != 0u && b2 != 0x80u);
            f3 |= (b3 != 0u);
            f3x |= (b3 != 0u && b3 != 0x3Fu);
        }
    }
    if (f0)  atomicOr(&fl[0], 1);
    if (f1)  atomicOr(&fl[1], 1);
    if (f2)  atomicOr(&fl[2], 1);
    if (f2x) atomicOr(&fl[3], 1);
    if (f3)  atomicOr(&fl[4], 1);
    if (f3x) atomicOr(&fl[5], 1);
    __syncthreads();
    if (t == 0) {
        int mode;
        if (!fl[1] && !fl[2] && !fl[4])                mode = 1;
        else if (!fl[0] && !fl[1] && !fl[3] && !fl[5]) mode = 2;
        else                                           mode = 0;
        g_mask_mode = mode;
    }
}

// ---------------------------------------------------------------------------
// k_cb: per code — cn2 (fp32) + bf16 hi/lo split of the codebook.
// ---------------------------------------------------------------------------
__global__ void k_cb(const float* __restrict__ cb) {
    int wid = threadIdx.x >> 5, ln = threadIdx.x & 31;
    int code = blockIdx.x * 8 + wid;
    const float4* r = (const float4*)(cb + (size_t)code * DIM);
    float4 a = r[ln], b = r[ln + 32];
    float s = a.x * a.x + a.y * a.y + a.z * a.z + a.w * a.w
            + b.x * b.x + b.y * b.y + b.z * b.z + b.w * b.w;
    #pragma unroll
    for (int off = 16; off; off >>= 1) s += __shfl_xor_sync(0xFFFFFFFFu, s, off);
    if (ln == 0) g_cn2[code] = 0.5f * s;

    size_t base = (size_t)code * 128;
    float v0[8] = {a.x, a.y, a.z, a.w, b.x, b.y, b.z, b.w};
    int idxs[4] = {2 * ln, 2 * ln + 1, 64 + 2 * ln, 64 + 2 * ln + 1};
    #pragma unroll
    for (int q = 0; q < 4; ++q) {
        float x = v0[2 * q], y = v0[2 * q + 1];
        __nv_bfloat162 hb = __floats2bfloat162_rn(x, y);
        float rx = x - __bfloat162float(hb.x);
        float ry = y - __bfloat162float(hb.y);
        __nv_bfloat162 lb = __floats2bfloat162_rn(rx, ry);
        g_cbhi[base + idxs[q]] = bf2u(hb);
        g_cblo[base + idxs[q]] = bf2u(lb);
    }
}

// ---------------------------------------------------------------------------
// k_gemm — the measured-best fp32 FFMA2 microkernel (round-4), standalone.
// Blocks [0,1024): z tile 64x256 -> rowz2 (fp32) + bf16 hi/lo z to global.
// Blocks [1024,1032): C_out = codebook @ W_out^T (fp32 to g_cout).
// ---------------------------------------------------------------------------
#define G_SM_HS 0
#define G_SM_WS 2176
#define G_SM_FLOATS (2176 + 8256)
#define G_SM_BYTES  (G_SM_FLOATS * 4)

__global__ void __launch_bounds__(256, 2)
k_gemm(const float* __restrict__ hidden, const float* __restrict__ codebook,
       const float* __restrict__ Win, const float* __restrict__ Wout)
{
    extern __shared__ float sm[];
    float* Hs = sm + G_SM_HS;
    float* Ws = sm + G_SM_WS;

    const int t   = threadIdx.x;
    const int rb  = t >> 4;
    const int ec  = t & 15;
    const int rb4 = rb << 2;
    const bool isVQ = (blockIdx.x < 1024);

    const float* src;
    const float* Wm;
    int n0;
    if (isVQ) { n0 = blockIdx.x * 64;          src = hidden   + (size_t)n0 * DIM; Wm = Win;  }
    else      { n0 = (blockIdx.x - 1024) * 64; src = codebook + (size_t)n0 * DIM; Wm = Wout; }

    ull accA[4][8];
    #pragma unroll
    for (int i = 0; i < 4; ++i)
        #pragma unroll
        for (int p = 0; p < 8; ++p) accA[i][p] = 0ull;

    for (int dk = 0; dk < 8; ++dk) {
        __syncthreads();
        #pragma unroll
        for (int i = 0; i < 2; ++i) {              // Hs: 64 rows x 32 dims, kk-major
            int id = i * 256 + t, r = id >> 3, kg = id & 7;
            float4 v = *(const float4*)(src + (size_t)r * DIM + dk * 32 + kg * 4);
            Hs[(kg * 4 + 0) * 68 + r] = v.x;
            Hs[(kg * 4 + 1) * 68 + r] = v.y;
            Hs[(kg * 4 + 2) * 68 + r] = v.z;
            Hs[(kg * 4 + 3) * 68 + r] = v.w;
        }
        #pragma unroll
        for (int i = 0; i < 8; ++i) {              // Ws: 256 cols x 32 dims, kk-major
            int id = i * 256 + t, e = id >> 3, kg = id & 7;
            float4 v = *(const float4*)(Wm + (size_t)e * DIM + dk * 32 + kg * 4);
            Ws[(kg * 4 + 0) * 258 + e] = v.x;
            Ws[(kg * 4 + 1) * 258 + e] = v.y;
            Ws[(kg * 4 + 2) * 258 + e] = v.z;
            Ws[(kg * 4 + 3) * 258 + e] = v.w;
        }
        __syncthreads();
        #pragma unroll 4
        for (int kk = 0; kk < 32; ++kk) {
            float4 h4 = *(const float4*)(Hs + kk * 68 + rb4);   // broadcast
            ull hz0 = pk2(h4.x), hz1 = pk2(h4.y), hz2 = pk2(h4.z), hz3 = pk2(h4.w);
            const float* wr = Ws + kk * 258 + 2 * ec;           // LDS.64, CF
            #pragma unroll
            for (int p = 0; p < 8; ++p) {
                ull wp = *(const ull*)(wr + 32 * p);
                fma2(accA[0][p], hz0, wp);
                fma2(accA[1][p], hz1, wp);
                fma2(accA[2][p], hz2, wp);
                fma2(accA[3][p], hz3, wp);
            }
        }
    }

    if (!isVQ) {  // C_out blocks
        #pragma unroll
        for (int p = 0; p < 8; ++p) {
            int e = 2 * ec + 32 * p;
            #pragma unroll
            for (int i = 0; i < 4; ++i) {
                float lo, hi; upk(accA[i][p], lo, hi);
                *(float2*)(g_cout + (size_t)(n0 + rb4 + i) * DIM + e) = make_float2(lo, hi);
            }
        }
        return;
    }

    // rowz2 from fp32 accs (fixed order, width-16 shfl across ec)
    float pz[4] = {0.f, 0.f, 0.f, 0.f};
    #pragma unroll
    for (int p = 0; p < 8; ++p)
        #pragma unroll
        for (int i = 0; i < 4; ++i) {
            float lo, hi; upk(accA[i][p], lo, hi);
            pz[i] = fmaf(lo, lo, pz[i]);
            pz[i] = fmaf(hi, hi, pz[i]);
        }
    #pragma unroll
    for (int i = 0; i < 4; ++i) {
        #pragma unroll
        for (int off = 8; off; off >>= 1)
            pz[i] += __shfl_down_sync(0xFFFFFFFFu, pz[i], off, 16);
    }
    if (ec == 0) {
        #pragma unroll
        for (int i = 0; i < 4; ++i) g_rowz2[n0 + rb4 + i] = pz[i];
    }

    // bf16 hi/lo split of z to global (pair cols 2ec+32p,+1 -> u32 idx ec+16p)
    #pragma unroll
    for (int p = 0; p < 8; ++p) {
        int ci = ec + 16 * p;
        #pragma unroll
        for (int i = 0; i < 4; ++i) {
            float lo, hi; upk(accA[i][p], lo, hi);
            __nv_bfloat162 hb = __floats2bfloat162_rn(lo, hi);
            float rl = lo - __bfloat162float(hb.x);
            float rh = hi - __bfloat162float(hb.y);
            __nv_bfloat162 lb = __floats2bfloat162_rn(rl, rh);
            size_t idx = (size_t)(n0 + rb4 + i) * 128 + ci;
            g_zhi[idx] = bf2u(hb);
            g_zlo[idx] = bf2u(lb);
        }
    }
}

// ---------------------------------------------------------------------------
// k_score — bf16 3-split scoring via mma.sync (HMMA), v2:
//  * double-buffered cp.async staging (1 sync/slice, LDG latency hidden)
//  * B fragments via ldmatrix.x4 (2 n8-tiles/load; LDSM instrs halved)
//  * cn2 via __ldg (no smem stage)
// CTA = 128 rows x 512 codes; warp = 16 rows. 48 flat slices (chunk,kc):
// kc 0-3 zh*ch, 4-7 zl*ch, 8-11 zh*cl; fp32 accum. Same accumulation order
// as the round-13 pass -> bit-identical idx/loss.
// ---------------------------------------------------------------------------
__global__ void __launch_bounds__(256, 2)
k_score()
{
    __shared__ __align__(16) unsigned char As[2][18432];  // 128 x 72 bf16 each
    __shared__ __align__(16) unsigned char Bs[2][18432];
    __shared__ float red[128];

    const int tid  = threadIdx.x;
    const int wid  = tid >> 5;
    const int lane = tid & 31;
    const int wr   = wid * 16;
    const int rowg = blockIdx.x * 128;
    const uint32_t As_b = smem_to_u32(As);
    const uint32_t Bs_b = smem_to_u32(Bs);

    // ldmatrix lane addressing:
    // A x4: row = wr + (lane&15), k-half = (lane&16)?16B:0.
    // B x4 (two n8-tiles per load): m0=(codes 0-7,k0-7), m1=(codes 0-7,k8-15),
    //   m2=(codes 8-15,k0-7), m3=(codes 8-15,k8-15).
    const uint32_t a_row   = (uint32_t)(wr + (lane & 15));
    const uint32_t a_koff  = (lane & 16) ? 16u : 0u;
    const uint32_t b4_row  = (uint32_t)((lane & 7) + 8 * ((lane >> 4) & 1));
    const uint32_t b4_koff = ((lane >> 3) & 1) ? 16u : 0u;

    // ---- async staging of slice s into buffer buf ----
    auto stage = [&](int s, int buf) {
        const int chunk = s / 12, kc = s % 12;
        const int seg = kc >> 2, k64 = kc & 3;
        const uint32_t* Asrc = (seg == 1) ? g_zlo : g_zhi;
        const uint32_t* Bsrc = (seg == 2) ? g_cblo : g_cbhi;
        const uint32_t abuf = As_b + (uint32_t)buf * 18432u;
        const uint32_t bbuf = Bs_b + (uint32_t)buf * 18432u;
        #pragma unroll
        for (int it = 0; it < 4; ++it) {
            int c16 = it * 256 + tid;            // 16B chunk id, 0..1023
            int row = c16 >> 3, j4 = (c16 & 7) << 2;
            const uint32_t* as = Asrc + (size_t)(rowg + row) * 128 + k64 * 32 + j4;
            const uint32_t* bs = Bsrc + (size_t)(chunk * 128 + row) * 128 + k64 * 32 + j4;
            uint32_t ad = abuf + (uint32_t)(row * 36 + j4) * 4u;
            uint32_t bd = bbuf + (uint32_t)(row * 36 + j4) * 4u;
            asm volatile("cp.async.cg.shared.global [%0], [%1], 16;" :: "r"(ad), "l"(as));
            asm volatile("cp.async.cg.shared.global [%0], [%1], 16;" :: "r"(bd), "l"(bs));
        }
        asm volatile("cp.async.commit_group;" ::: "memory");
    };

    float best0 = -3.0e38f, best1 = -3.0e38f;
    int   bi0 = 0, bi1 = 0;
    float acc[16][4];

    stage(0, 0);
    asm volatile("cp.async.wait_group 0;" ::: "memory");
    __syncthreads();

    for (int s = 0; s < 48; ++s) {
        const int buf = s & 1;
        const int kc  = s % 12;
        if (s + 1 < 48) stage(s + 1, buf ^ 1);

        if (kc == 0) {
            #pragma unroll
            for (int j = 0; j < 16; ++j) {
                acc[j][0] = 0.f; acc[j][1] = 0.f; acc[j][2] = 0.f; acc[j][3] = 0.f;
            }
        }

        const uint32_t abase = As_b + (uint32_t)buf * 18432u + a_row * 144u + a_koff;
        const uint32_t bbase = Bs_b + (uint32_t)buf * 18432u + b4_row * 144u + b4_koff;
        #pragma unroll
        for (int k8 = 0; k8 < 4; ++k8) {
            uint32_t a0, a1, a2, a3;
            asm volatile(
                "ldmatrix.sync.aligned.m8n8.x4.shared.b16 {%0,%1,%2,%3}, [%4];"
                : "=r"(a0), "=r"(a1), "=r"(a2), "=r"(a3)
                : "r"(abase + (uint32_t)k8 * 32u));
            uint32_t bb = bbase + (uint32_t)k8 * 32u;
            #pragma unroll
            for (int jp = 0; jp < 8; ++jp) {
                uint32_t b0, b1, b2, b3;
                asm volatile(
                    "ldmatrix.sync.aligned.m8n8.x4.shared.b16 {%0,%1,%2,%3}, [%4];"
                    : "=r"(b0), "=r"(b1), "=r"(b2), "=r"(b3)
                    : "r"(bb + (uint32_t)jp * 2304u));     // 16 rows * 144B
                asm volatile(
                    "mma.sync.aligned.m16n8k16.row.col.f32.bf16.bf16.f32 "
                    "{%0,%1,%2,%3}, {%4,%5,%6,%7}, {%8,%9}, {%0,%1,%2,%3};"
                    : "+f"(acc[2*jp][0]), "+f"(acc[2*jp][1]),
                      "+f"(acc[2*jp][2]), "+f"(acc[2*jp][3])
                    : "r"(a0), "r"(a1), "r"(a2), "r"(a3), "r"(b0), "r"(b1));
                asm volatile(
                    "mma.sync.aligned.m16n8k16.row.col.f32.bf16.bf16.f32 "
                    "{%0,%1,%2,%3}, {%4,%5,%6,%7}, {%8,%9}, {%0,%1,%2,%3};"
                    : "+f"(acc[2*jp+1][0]), "+f"(acc[2*jp+1][1]),
                      "+f"(acc[2*jp+1][2]), "+f"(acc[2*jp+1][3])
                    : "r"(a0), "r"(a1), "r"(a2), "r"(a3), "r"(b2), "r"(b3));
            }
        }

        if (kc == 11) {
            const int chunk = s / 12;
            #pragma unroll
            for (int j = 0; j < 16; ++j) {
                int cl = j * 8 + ((lane & 3) << 1);
                int code = chunk * 128 + cl;
                float h0 = __ldg(&g_cn2[code]), h1 = __ldg(&g_cn2[code + 1]);
                float s00 = acc[j][0] - h0, s01 = acc[j][1] - h1;
                float s10 = acc[j][2] - h0, s11 = acc[j][3] - h1;
                if (s00 > best0 || (s00 == best0 && code     < bi0)) { best0 = s00; bi0 = code;     }
                if (s01 > best0 || (s01 == best0 && code + 1 < bi0)) { best0 = s01; bi0 = code + 1; }
                if (s10 > best1 || (s10 == best1 && code     < bi1)) { best1 = s10; bi1 = code;     }
                if (s11 > best1 || (s11 == best1 && code + 1 < bi1)) { best1 = s11; bi1 = code + 1; }
            }
        }

        asm volatile("cp.async.wait_group 0;" ::: "memory");
        __syncthreads();
    }

    // reduce across the 4 lanes sharing l/4 (disjoint code subsets per lane)
    #pragma unroll
    for (int off = 1; off <= 2; off <<= 1) {
        float s = __shfl_xor_sync(0xFFFFFFFFu, best0, off);
        int   i = __shfl_xor_sync(0xFFFFFFFFu, bi0,   off);
        if (s > best0 || (s == best0 && i < bi0)) { best0 = s; bi0 = i; }
        s = __shfl_xor_sync(0xFFFFFFFFu, best1, off);
        i = __shfl_xor_sync(0xFFFFFFFFu, bi1,   off);
        if (s > best1 || (s == best1 && i < bi1)) { best1 = s; bi1 = i; }
    }
    if ((lane & 3) == 0) {
        int r0 = wr + (lane >> 2);
        int r1 = r0 + 8;
        g_idx[rowg + r0] = bi0;
        g_idx[rowg + r1] = bi1;
        red[r0] = g_rowz2[rowg + r0] - 2.0f * best0;   // |z - c*|^2
        red[r1] = g_rowz2[rowg + r1] - 2.0f * best1;
    }
    __syncthreads();
    if (tid == 0) {
        float s = 0.0f;
        for (int j = 0; j < 128; ++j) s += red[j];     // fixed order
        g_partial[blockIdx.x] = s;
    }
}

// ---------------------------------------------------------------------------
// Epilogue: blocks [0,8192): h = hidden + mask*C_out[idx]; LayerNorm (warp/row).
// Block 8192: vq_loss = 1.25 * sum(g_partial[0..511]) / (N*D).
// ---------------------------------------------------------------------------
__global__ void __launch_bounds__(256)
k_pass2(const float* __restrict__ hidden, const void* __restrict__ maskp,
        const float* __restrict__ gamma, const float* __restrict__ beta,
        float* __restrict__ out, int has_loss)
{
    if (blockIdx.x == 8192) {
        __shared__ float red[256];
        int t = threadIdx.x;
        red[t] = g_partial[t] + g_partial[t + 256];
        __syncthreads();
        for (int off = 128; off; off >>= 1) {
            if (t < off) red[t] += red[t + off];
            __syncthreads();
        }
        if (t == 0 && has_loss) out[ND] = 1.25f * red[0] / (float)ND;
        return;
    }

    int w = threadIdx.x >> 5, ln = threadIdx.x & 31;
    int n = blockIdx.x * 8 + w;
    int code = g_idx[n];
    int mode = g_mask_mode;
    float m;
    if (mode == 1)      m = ((const int*)maskp)[n] ? 1.0f : 0.0f;
    else if (mode == 2) m = ((const float*)maskp)[n];
    else                m = ((const unsigned char*)maskp)[n] ? 1.0f : 0.0f;

    const float4* hr = (const float4*)(hidden + (size_t)n * DIM);
    const float4* cr = (const float4*)(g_cout + (size_t)code * DIM);
    float4 h0 = hr[ln],      h1 = hr[ln + 32];
    float4 c0 = cr[ln],      c1 = cr[ln + 32];
    h0.x = fmaf(m, c0.x, h0.x); h0.y = fmaf(m, c0.y, h0.y);
    h0.z = fmaf(m, c0.z, h0.z); h0.w = fmaf(m, c0.w, h0.w);
    h1.x = fmaf(m, c1.x, h1.x); h1.y = fmaf(m, c1.y, h1.y);
    h1.z = fmaf(m, c1.z, h1.z); h1.w = fmaf(m, c1.w, h1.w);

    float sum = h0.x + h0.y + h0.z + h0.w + h1.x + h1.y + h1.z + h1.w;
    #pragma unroll
    for (int off = 16; off; off >>= 1) sum += __shfl_xor_sync(0xFFFFFFFFu, sum, off);
    float mu = sum * (1.0f / 256.0f);

    float d0 = h0.x - mu, d1 = h0.y - mu, d2 = h0.z - mu, d3 = h0.w - mu;
    float d4 = h1.x - mu, d5 = h1.y - mu, d6 = h1.z - mu, d7 = h1.w - mu;
    float vs = d0*d0 + d1*d1 + d2*d2 + d3*d3 + d4*d4 + d5*d5 + d6*d6 + d7*d7;
    #pragma unroll
    for (int off = 16; off; off >>= 1) vs += __shfl_xor_sync(0xFFFFFFFFu, vs, off);
    float inv = rsqrtf(vs * (1.0f / 256.0f) + 1e-5f);

    float4 g0 = ((const float4*)gamma)[ln], g1 = ((const float4*)gamma)[ln + 32];
    float4 b0 = ((const float4*)beta)[ln],  b1 = ((const float4*)beta)[ln + 32];
    float4 o0 = make_float4(fmaf(d0 * inv, g0.x, b0.x), fmaf(d1 * inv, g0.y, b0.y),
                            fmaf(d2 * inv, g0.z, b0.z), fmaf(d3 * inv, g0.w, b0.w));
    float4 o1 = make_float4(fmaf(d4 * inv, g1.x, b1.x), fmaf(d5 * inv, g1.y, b1.y),
                            fmaf(d6 * inv, g1.z, b1.z), fmaf(d7 * inv, g1.w, b1.w));
    float4* orow = (float4*)(out + (size_t)n * DIM);
    orow[ln]      = o0;
    orow[ln + 32] = o1;
}

// ---------------------------------------------------------------------------
extern "C" void kernel_launch(void* const* d_in, const int* in_sizes, int n_in,
                              void* d_out, int out_size) {
    const float* hidden   = (const float*)d_in[0];
    const void*  mask     = d_in[1];
    const float* codebook = (const float*)d_in[2];
    const float* Win      = (const float*)d_in[3];
    const float* Wout     = (const float*)d_in[4];
    const float* gamma    = (const float*)d_in[5];
    const float* beta     = (const float*)d_in[6];
    float* out = (float*)d_out;

    // global launch indices (harness emits 2 first): detect=2, cb=3, gemm=4,
    // score=5 (ncu -s 5 capture target), pass2=6.
    k_detect<<<1, 256>>>((const unsigned char*)mask);
    k_cb<<<64, 256>>>(codebook);
    k_gemm<<<1032, 256, G_SM_BYTES>>>(hidden, codebook, Win, Wout);
    k_score<<<512, 256>>>();
    k_pass2<<<8193, 256>>>(hidden, mask, gamma, beta, out, (out_size > ND) ? 1 : 0);
}